// round 8
// baseline (speedup 1.0000x reference)
#include <cuda_runtime.h>
#include <cstdint>

#define NNODES 2048
#define JDIM   768      // F_IN * T = 32*24
#define KCHEB  3
#define BATCH  16
#define FOUT   64
#define TDIM   24

// 302 MB scratch: rhs[b][m][k][f*24+t]   (b*2048+m)*2304 + k*768 + f*24 + t
__device__ float g_rhs[(size_t)BATCH * NNODES * KCHEB * JDIM];

__device__ __forceinline__ uint32_t f2tf(float f) {
    uint32_t u;
    asm("cvt.rna.tf32.f32 %0, %1;" : "=r"(u) : "f"(f));
    return u;
}

__device__ __forceinline__ void mma_tf32(float d[4], const uint32_t a[4], const uint32_t b[2]) {
    asm("mma.sync.aligned.m16n8k8.row.col.f32.tf32.tf32.f32 "
        "{%0,%1,%2,%3}, {%4,%5,%6,%7}, {%8,%9}, {%0,%1,%2,%3};"
        : "+f"(d[0]), "+f"(d[1]), "+f"(d[2]), "+f"(d[3])
        : "r"(a[0]), "r"(a[1]), "r"(a[2]), "r"(a[3]),
          "r"(b[0]), "r"(b[1]));
}

// ---------------------------------------------------------------------------
// Stage 1: per (k,b): rhs[m, j] = sum_n (cheb[k][n][m] * att[b][n][m]) * x[b][n][j]
// CTA tile 128(m) x 128(j), K-chunk 32(n). 256 threads = 8 warps (4x2),
// warp tile 32x64 -> 2 m-frags x 8 n-frags of m16n8k8 tf32 mma.
// ---------------------------------------------------------------------------
__global__ void __launch_bounds__(256)
stage1_kernel(const float* __restrict__ x,
              const float* __restrict__ att,
              const float* __restrict__ cheb)
{
    const int k  = blockIdx.z % KCHEB;
    const int b  = blockIdx.z / KCHEB;
    const int m0 = blockIdx.y << 7;
    const int j0 = blockIdx.x << 7;

    const float* __restrict__ Ac = cheb + (size_t)k * NNODES * NNODES;
    const float* __restrict__ Aa = att  + (size_t)b * NNODES * NNODES;
    const float* __restrict__ Xp = x    + (size_t)b * NNODES * JDIM;

    // padded to 136 words: fragment-read stride mod 32 == 8 -> conflict-free
    __shared__ uint32_t As[32][136];   // As[n][m]  (tf32 of cheb*att)
    __shared__ uint32_t Bs[32][136];   // Bs[n][j]  (tf32 of x)

    const int tid  = threadIdx.x;
    const int lane = tid & 31;
    const int warp = tid >> 5;
    const int wm = (warp >> 1) << 5;   // 0,32,64,96
    const int wn = (warp & 1) << 6;    // 0,64
    const int g  = lane >> 2;          // 0..7
    const int ti = lane & 3;           // 0..3

    float acc[2][8][4];
#pragma unroll
    for (int i = 0; i < 2; ++i)
#pragma unroll
        for (int j = 0; j < 8; ++j)
#pragma unroll
            for (int c = 0; c < 4; ++c) acc[i][j][c] = 0.0f;

    float4 rc[4], ra[4], rx[4];

    auto load_tile = [&](int n0) {
#pragma unroll
        for (int i = 0; i < 4; ++i) {
            const int l  = tid + (i << 8);
            const int nr = l >> 5;        // 0..31  (n within chunk)
            const int c4 = l & 31;        // float4 column
            const size_t roA = (size_t)(n0 + nr) * NNODES + m0;
            rc[i] = *(reinterpret_cast<const float4*>(Ac + roA) + c4);
            ra[i] = *(reinterpret_cast<const float4*>(Aa + roA) + c4);
            rx[i] = *(reinterpret_cast<const float4*>(Xp + (size_t)(n0 + nr) * JDIM + j0) + c4);
        }
    };

    auto store_tile = [&]() {
#pragma unroll
        for (int i = 0; i < 4; ++i) {
            const int l  = tid + (i << 8);
            const int nr = l >> 5;
            const int c4 = l & 31;
            uint4 ua, ub;
            ua.x = f2tf(rc[i].x * ra[i].x);
            ua.y = f2tf(rc[i].y * ra[i].y);
            ua.z = f2tf(rc[i].z * ra[i].z);
            ua.w = f2tf(rc[i].w * ra[i].w);
            ub.x = f2tf(rx[i].x);
            ub.y = f2tf(rx[i].y);
            ub.z = f2tf(rx[i].z);
            ub.w = f2tf(rx[i].w);
            *reinterpret_cast<uint4*>(&As[nr][c4 << 2]) = ua;
            *reinterpret_cast<uint4*>(&Bs[nr][c4 << 2]) = ub;
        }
    };

    auto compute = [&]() {
#pragma unroll
        for (int s = 0; s < 4; ++s) {          // 4 k-steps of 8 within the 32-chunk
            const int ks = s << 3;
            uint32_t af[2][4], bf[8][2];
#pragma unroll
            for (int i = 0; i < 2; ++i) {
                const int mi = wm + (i << 4);
                af[i][0] = As[ks + ti][mi + g];
                af[i][1] = As[ks + ti][mi + g + 8];
                af[i][2] = As[ks + ti + 4][mi + g];
                af[i][3] = As[ks + ti + 4][mi + g + 8];
            }
#pragma unroll
            for (int j = 0; j < 8; ++j) {
                const int nj = wn + (j << 3);
                bf[j][0] = Bs[ks + ti][nj + g];
                bf[j][1] = Bs[ks + ti + 4][nj + g];
            }
#pragma unroll
            for (int i = 0; i < 2; ++i)
#pragma unroll
                for (int j = 0; j < 8; ++j)
                    mma_tf32(acc[i][j], af[i], bf[j]);
        }
    };

    load_tile(0);
    store_tile();
    __syncthreads();

    for (int n0 = 0; n0 < NNODES; n0 += 32) {
        const bool has_next = (n0 + 32) < NNODES;
        if (has_next) load_tile(n0 + 32);   // LDGs in flight during compute
        compute();
        __syncthreads();
        if (has_next) {
            store_tile();
            __syncthreads();
        }
    }

    // Epilogue: acc layout c0:(g,2ti) c1:(g,2ti+1) c2:(g+8,2ti) c3:(g+8,2ti+1)
#pragma unroll
    for (int i = 0; i < 2; ++i) {
#pragma unroll
        for (int h = 0; h < 2; ++h) {
            const int row = m0 + wm + (i << 4) + g + (h << 3);
            float* orow = g_rhs
                        + (((size_t)b * NNODES + row) * KCHEB + k) * JDIM
                        + j0 + wn + (ti << 1);
#pragma unroll
            for (int j = 0; j < 8; ++j) {
                float2 v = make_float2(acc[i][j][h << 1], acc[i][j][(h << 1) + 1]);
                *reinterpret_cast<float2*>(orow + (j << 3)) = v;
            }
        }
    }
}

// ---------------------------------------------------------------------------
// Stage 2: out[b,m,o,t] = relu( sum_{k,f} rhs[b,m,k,f,t] * Theta[k,f,o] )
// 128 threads per CTA handle 2 (b,m) pairs; per pair 64 threads cover
// 64(o) x 24(t) in 4x6 register blocks. fp32, FMA-bound.
// ---------------------------------------------------------------------------
__global__ void __launch_bounds__(128)
stage2_kernel(const float* __restrict__ Theta, float* __restrict__ out)
{
    __shared__ float sW[KCHEB * 32 * FOUT];   // 6144 floats, layout [kf][o]
    __shared__ float sR[2 * KCHEB * JDIM];    // 2 x 2304 floats, layout [kf][t]

    const int tid = threadIdx.x;

#pragma unroll
    for (int i = 0; i < 12; ++i) {
        const int l = (tid + (i << 7)) << 2;
        *reinterpret_cast<float4*>(&sW[l]) =
            *reinterpret_cast<const float4*>(Theta + l);
    }
    const size_t bm0 = (size_t)blockIdx.x << 1;
    const float* rbase = g_rhs + bm0 * (KCHEB * JDIM);
#pragma unroll
    for (int i = 0; i < 9; ++i) {
        const int l = (tid + (i << 7)) << 2;
        *reinterpret_cast<float4*>(&sR[l]) =
            *reinterpret_cast<const float4*>(rbase + l);
    }
    __syncthreads();

    const int sub = tid >> 6;            // which (b,m) of the pair
    const int t64 = tid & 63;
    const int o0  = (t64 & 15) << 2;     // 4 consecutive o per thread
    const int tb  = (t64 >> 4) * 6;      // 6 consecutive t per thread
    const float* R = &sR[sub * (KCHEB * JDIM)];

    float acc[4][6];
#pragma unroll
    for (int i = 0; i < 4; ++i)
#pragma unroll
        for (int j = 0; j < 6; ++j) acc[i][j] = 0.0f;

#pragma unroll 4
    for (int kf = 0; kf < 96; ++kf) {
        const float4 w = *reinterpret_cast<const float4*>(&sW[(kf << 6) + o0]);
        const float* rr = &R[kf * TDIM + tb];
#pragma unroll
        for (int j = 0; j < 6; ++j) {
            const float rv = rr[j];
            acc[0][j] = fmaf(w.x, rv, acc[0][j]);
            acc[1][j] = fmaf(w.y, rv, acc[1][j]);
            acc[2][j] = fmaf(w.z, rv, acc[2][j]);
            acc[3][j] = fmaf(w.w, rv, acc[3][j]);
        }
    }

    float* obase = out + (bm0 + sub) * (FOUT * TDIM);
#pragma unroll
    for (int i = 0; i < 4; ++i) {
        float* orow = obase + (o0 + i) * TDIM + tb;
#pragma unroll
        for (int j = 0; j < 6; j += 2) {
            float2 v = make_float2(fmaxf(acc[i][j],     0.0f),
                                   fmaxf(acc[i][j + 1], 0.0f));
            *reinterpret_cast<float2*>(orow + j) = v;
        }
    }
}

// ---------------------------------------------------------------------------
extern "C" void kernel_launch(void* const* d_in, const int* in_sizes, int n_in,
                              void* d_out, int out_size)
{
    (void)in_sizes; (void)n_in; (void)out_size;
    const float* x     = (const float*)d_in[0];   // (16,2048,32,24)
    const float* att   = (const float*)d_in[1];   // (16,2048,2048)
    const float* cheb  = (const float*)d_in[2];   // (3,2048,2048)
    const float* Theta = (const float*)d_in[3];   // (3,32,64)
    float* out = (float*)d_out;                   // (16,2048,64,24)

    dim3 g1(JDIM / 128, NNODES / 128, KCHEB * BATCH);   // (6, 16, 48)
    stage1_kernel<<<g1, 256>>>(x, att, cheb);
    stage2_kernel<<<(BATCH * NNODES) / 2, 128>>>(Theta, out);
}

// round 10
// speedup vs baseline: 1.3393x; 1.3393x over previous
#include <cuda_runtime.h>
#include <cuda_fp16.h>
#include <cstdint>

#define NNODES 2048
#define JDIM   768      // F_IN * T = 32*24
#define KCHEB  3
#define BATCH  16
#define FOUT   64
#define TDIM   24

// 302 MB scratch: rhs[b][m][k][f*24+t]
__device__ float g_rhs[(size_t)BATCH * NNODES * KCHEB * JDIM];

__device__ __forceinline__ uint32_t pack_h2(float lo, float hi) {
    __half2 h = __floats2half2_rn(lo, hi);
    return *reinterpret_cast<uint32_t*>(&h);
}

__device__ __forceinline__ void mma_fp16(float d[4], const uint32_t a[4], const uint32_t b[2]) {
    asm("mma.sync.aligned.m16n8k16.row.col.f32.f16.f16.f32 "
        "{%0,%1,%2,%3}, {%4,%5,%6,%7}, {%8,%9}, {%0,%1,%2,%3};"
        : "+f"(d[0]), "+f"(d[1]), "+f"(d[2]), "+f"(d[3])
        : "r"(a[0]), "r"(a[1]), "r"(a[2]), "r"(a[3]),
          "r"(b[0]), "r"(b[1]));
}

// ---------------------------------------------------------------------------
// Stage 1: per (k,b): rhs[m,j] = sum_n (cheb[k][n][m]*att[b][n][m]) * x[b][n][j]
// fp16 m16n8k16 mma. CTA tile 128(m) x 128(j), K-chunk 32(n), 256 threads =
// 8 warps (4x2), warp tile 32x64 -> 2 m-frags x 8 j-frags, 2 k-steps/chunk.
// Smem holds half2 packed along n: As[np][m] = {v(2np), v(2np+1)}.
// ---------------------------------------------------------------------------
__global__ void __launch_bounds__(256)
stage1_kernel(const float* __restrict__ x,
              const float* __restrict__ att,
              const float* __restrict__ cheb)
{
    const int k  = blockIdx.z % KCHEB;
    const int b  = blockIdx.z / KCHEB;
    const int m0 = blockIdx.y << 7;
    const int j0 = blockIdx.x << 7;

    const float* __restrict__ Ac = cheb + (size_t)k * NNODES * NNODES;
    const float* __restrict__ Aa = att  + (size_t)b * NNODES * NNODES;
    const float* __restrict__ Xp = x    + (size_t)b * NNODES * JDIM;

    // pitch 136 words (136 mod 32 == 8): fragment reads (ti*136 + g) conflict-free
    __shared__ uint32_t As[16][136];   // half2{prod(n),prod(n+1)} indexed [np][m]
    __shared__ uint32_t Bs[16][136];   // half2{x(n),x(n+1)}       indexed [np][j]

    const int tid  = threadIdx.x;
    const int lane = tid & 31;
    const int warp = tid >> 5;
    const int wm = (warp >> 1) << 5;   // 0,32,64,96
    const int wn = (warp & 1) << 6;    // 0,64
    const int g  = lane >> 2;          // 0..7
    const int ti = lane & 3;           // 0..3

    float acc[2][8][4];
#pragma unroll
    for (int i = 0; i < 2; ++i)
#pragma unroll
        for (int j = 0; j < 8; ++j)
#pragma unroll
            for (int c = 0; c < 4; ++c) acc[i][j][c] = 0.0f;

    // raw prefetch registers: 2 units/thread, each unit = (np, quad-col)
    float4 rc0[2], rc1[2], ra0[2], ra1[2], rx0[2], rx1[2];

    auto load_tile = [&](int n0) {
#pragma unroll
        for (int i = 0; i < 2; ++i) {
            const int u  = tid + (i << 8);   // 0..511
            const int np = u >> 5;           // 0..15
            const int q  = u & 31;           // float4 column
            const size_t roA = (size_t)(n0 + (np << 1)) * NNODES + m0;
            rc0[i] = *((const float4*)(Ac + roA) + q);
            rc1[i] = *((const float4*)(Ac + roA + NNODES) + q);
            ra0[i] = *((const float4*)(Aa + roA) + q);
            ra1[i] = *((const float4*)(Aa + roA + NNODES) + q);
            const size_t roX = (size_t)(n0 + (np << 1)) * JDIM + j0;
            rx0[i] = *((const float4*)(Xp + roX) + q);
            rx1[i] = *((const float4*)(Xp + roX + JDIM) + q);
        }
    };

    auto store_tile = [&]() {
#pragma unroll
        for (int i = 0; i < 2; ++i) {
            const int u  = tid + (i << 8);
            const int np = u >> 5;
            const int q  = u & 31;
            uint4 ua, ub;
            ua.x = pack_h2(rc0[i].x * ra0[i].x, rc1[i].x * ra1[i].x);
            ua.y = pack_h2(rc0[i].y * ra0[i].y, rc1[i].y * ra1[i].y);
            ua.z = pack_h2(rc0[i].z * ra0[i].z, rc1[i].z * ra1[i].z);
            ua.w = pack_h2(rc0[i].w * ra0[i].w, rc1[i].w * ra1[i].w);
            ub.x = pack_h2(rx0[i].x, rx1[i].x);
            ub.y = pack_h2(rx0[i].y, rx1[i].y);
            ub.z = pack_h2(rx0[i].z, rx1[i].z);
            ub.w = pack_h2(rx0[i].w, rx1[i].w);
            *reinterpret_cast<uint4*>(&As[np][q << 2]) = ua;
            *reinterpret_cast<uint4*>(&Bs[np][q << 2]) = ub;
        }
    };

    auto compute = [&]() {
#pragma unroll
        for (int s = 0; s < 2; ++s) {          // 2 k-steps of 16 per 32-chunk
            const int r0 = (s << 3) + ti;      // np row for k = 2ti(+16s)
            const int r1 = r0 + 4;             // np row for k = 2ti+8(+16s)
            uint32_t af[2][4], bf[8][2];
#pragma unroll
            for (int i = 0; i < 2; ++i) {
                const int mi = wm + (i << 4);
                af[i][0] = As[r0][mi + g];
                af[i][1] = As[r0][mi + g + 8];
                af[i][2] = As[r1][mi + g];
                af[i][3] = As[r1][mi + g + 8];
            }
#pragma unroll
            for (int j = 0; j < 8; ++j) {
                const int nj = wn + (j << 3);
                bf[j][0] = Bs[r0][nj + g];
                bf[j][1] = Bs[r1][nj + g];
            }
#pragma unroll
            for (int i = 0; i < 2; ++i)
#pragma unroll
                for (int j = 0; j < 8; ++j)
                    mma_fp16(acc[i][j], af[i], bf[j]);
        }
    };

    load_tile(0);
    store_tile();
    __syncthreads();

    for (int n0 = 0; n0 < NNODES; n0 += 32) {
        const bool has_next = (n0 + 32) < NNODES;
        if (has_next) load_tile(n0 + 32);   // LDGs in flight during compute
        compute();
        __syncthreads();
        if (has_next) {
            store_tile();
            __syncthreads();
        }
    }

    // Epilogue: acc c0:(g,2ti) c1:(g,2ti+1) c2:(g+8,2ti) c3:(g+8,2ti+1)
#pragma unroll
    for (int i = 0; i < 2; ++i) {
#pragma unroll
        for (int h = 0; h < 2; ++h) {
            const int row = m0 + wm + (i << 4) + g + (h << 3);
            float* orow = g_rhs
                        + (((size_t)b * NNODES + row) * KCHEB + k) * JDIM
                        + j0 + wn + (ti << 1);
#pragma unroll
            for (int j = 0; j < 8; ++j) {
                float2 v = make_float2(acc[i][j][h << 1], acc[i][j][(h << 1) + 1]);
                *reinterpret_cast<float2*>(orow + (j << 3)) = v;
            }
        }
    }
}

// ---------------------------------------------------------------------------
// Stage 2: out[b,m,o,t] = relu( sum_{k,f} rhs[b,m,k,f,t] * Theta[k,f,o] )
// ---------------------------------------------------------------------------
__global__ void __launch_bounds__(128)
stage2_kernel(const float* __restrict__ Theta, float* __restrict__ out)
{
    __shared__ float sW[KCHEB * 32 * FOUT];   // [kf][o]
    __shared__ float sR[2 * KCHEB * JDIM];    // 2 x [kf][t]

    const int tid = threadIdx.x;

#pragma unroll
    for (int i = 0; i < 12; ++i) {
        const int l = (tid + (i << 7)) << 2;
        *(float4*)&sW[l] = *(const float4*)(Theta + l);
    }
    const size_t bm0 = (size_t)blockIdx.x << 1;
    const float* rbase = g_rhs + bm0 * (KCHEB * JDIM);
#pragma unroll
    for (int i = 0; i < 9; ++i) {
        const int l = (tid + (i << 7)) << 2;
        *(float4*)&sR[l] = *(const float4*)(rbase + l);
    }
    __syncthreads();

    const int sub = tid >> 6;
    const int t64 = tid & 63;
    const int o0  = (t64 & 15) << 2;
    const int tb  = (t64 >> 4) * 6;
    const float* R = &sR[sub * (KCHEB * JDIM)];

    float acc[4][6];
#pragma unroll
    for (int i = 0; i < 4; ++i)
#pragma unroll
        for (int j = 0; j < 6; ++j) acc[i][j] = 0.0f;

#pragma unroll 4
    for (int kf = 0; kf < 96; ++kf) {
        const float4 wv = *(const float4*)&sW[(kf << 6) + o0];
        const float* rr = &R[kf * TDIM + tb];
#pragma unroll
        for (int j = 0; j < 6; ++j) {
            const float rv = rr[j];
            acc[0][j] = fmaf(wv.x, rv, acc[0][j]);
            acc[1][j] = fmaf(wv.y, rv, acc[1][j]);
            acc[2][j] = fmaf(wv.z, rv, acc[2][j]);
            acc[3][j] = fmaf(wv.w, rv, acc[3][j]);
        }
    }

    float* obase = out + (bm0 + sub) * (FOUT * TDIM);
#pragma unroll
    for (int i = 0; i < 4; ++i) {
        float* orow = obase + (o0 + i) * TDIM + tb;
#pragma unroll
        for (int j = 0; j < 6; j += 2)
            *(float2*)(orow + j) = make_float2(fmaxf(acc[i][j],     0.0f),
                                               fmaxf(acc[i][j + 1], 0.0f));
    }
}

// ---------------------------------------------------------------------------
extern "C" void kernel_launch(void* const* d_in, const int* in_sizes, int n_in,
                              void* d_out, int out_size)
{
    (void)in_sizes; (void)n_in; (void)out_size;
    const float* x     = (const float*)d_in[0];   // (16,2048,32,24)
    const float* att   = (const float*)d_in[1];   // (16,2048,2048)
    const float* cheb  = (const float*)d_in[2];   // (3,2048,2048)
    const float* Theta = (const float*)d_in[3];   // (3,32,64)
    float* out = (float*)d_out;                   // (16,2048,64,24)

    dim3 g1(JDIM / 128, NNODES / 128, KCHEB * BATCH);   // (6, 16, 48)
    stage1_kernel<<<g1, 256>>>(x, att, cheb);
    stage2_kernel<<<(BATCH * NNODES) / 2, 128>>>(Theta, out);
}

// round 11
// speedup vs baseline: 1.8993x; 1.4181x over previous
#include <cuda_runtime.h>
#include <cuda_fp16.h>
#include <cstdint>

#define NNODES 2048
#define JDIM   768      // F_IN * T = 32*24
#define KCHEB  3
#define BATCH  16
#define FOUT   64
#define TDIM   24

// 302 MB scratch: rhs[b][m][k][f*24+t]
__device__ float g_rhs[(size_t)BATCH * NNODES * KCHEB * JDIM];
// 50 MB pre-packed x: half2{x[b][2np][j], x[b][2np+1][j]} at [b][np][j]
__device__ uint32_t g_xh[(size_t)BATCH * (NNODES / 2) * JDIM];

__device__ __forceinline__ uint32_t pack_h2(float lo, float hi) {
    __half2 h = __floats2half2_rn(lo, hi);
    return *reinterpret_cast<uint32_t*>(&h);
}
__device__ __forceinline__ uint32_t smem_u32(const void* p) {
    uint32_t a;
    asm("{ .reg .u64 t; cvta.to.shared.u64 t, %1; cvt.u32.u64 %0, t; }" : "=r"(a) : "l"(p));
    return a;
}
__device__ __forceinline__ void cp16(uint32_t dst, const void* src) {
    asm volatile("cp.async.ca.shared.global [%0], [%1], 16;" :: "r"(dst), "l"(src) : "memory");
}
__device__ __forceinline__ void mma_fp16(float d[4], const uint32_t a[4], const uint32_t b[2]) {
    asm("mma.sync.aligned.m16n8k16.row.col.f32.f16.f16.f32 "
        "{%0,%1,%2,%3}, {%4,%5,%6,%7}, {%8,%9}, {%0,%1,%2,%3};"
        : "+f"(d[0]), "+f"(d[1]), "+f"(d[2]), "+f"(d[3])
        : "r"(a[0]), "r"(a[1]), "r"(a[2]), "r"(a[3]),
          "r"(b[0]), "r"(b[1]));
}

// ---------------------------------------------------------------------------
// Prepack: g_xh[b][np][j] = half2(x[b][2np][j], x[b][2np+1][j])
// ---------------------------------------------------------------------------
__global__ void __launch_bounds__(256)
prepack_kernel(const float* __restrict__ x)
{
    const int idx = blockIdx.x * 256 + threadIdx.x;   // over 16*1024*192 float4s
    const int b  = idx / (1024 * 192);
    const int r  = idx % (1024 * 192);
    const int np = r / 192;
    const int j4 = (r % 192) << 2;
    const size_t s0 = (size_t)(b * NNODES + (np << 1)) * JDIM + j4;
    const float4 a0 = *(const float4*)(x + s0);
    const float4 a1 = *(const float4*)(x + s0 + JDIM);
    uint4 o;
    o.x = pack_h2(a0.x, a1.x);  o.y = pack_h2(a0.y, a1.y);
    o.z = pack_h2(a0.z, a1.z);  o.w = pack_h2(a0.w, a1.w);
    *(uint4*)(g_xh + (size_t)(b * 1024 + np) * JDIM + j4) = o;
}

// ---------------------------------------------------------------------------
// Stage 1: per (k,b): rhs[m,j] = sum_n (cheb[k][n][m]*att[b][n][m]) * x[b][n][j]
// fp16 m16n8k16. CTA tile 128(m) x 256(j), K-chunk 32(n), 256 threads =
// 8 warps as 2(m) x 4(j); warp tile 64m x 64j -> 4 m-frags x 8 j-frags.
// Double-buffered smem, cp.async B from prepacked g_xh, 1 sync per chunk.
// ---------------------------------------------------------------------------
__global__ void __launch_bounds__(256)
stage1_kernel(const float* __restrict__ att,
              const float* __restrict__ cheb)
{
    const int k  = blockIdx.z % KCHEB;
    const int b  = blockIdx.z / KCHEB;
    const int m0 = blockIdx.y << 7;
    const int j0 = blockIdx.x << 8;

    const float* __restrict__ Ac = cheb + (size_t)k * NNODES * NNODES;
    const float* __restrict__ Aa = att  + (size_t)b * NNODES * NNODES;

    // pitches 136 / 264 words (mod 32 == 8): fragment reads conflict-free
    __shared__ __align__(16) uint32_t As[2][16][136];  // half2 prod, [np][m]
    __shared__ __align__(16) uint32_t Bs[2][16][264];  // half2 x,    [np][j]

    const int tid  = threadIdx.x;
    const int lane = tid & 31;
    const int warp = tid >> 5;
    const int wm = (warp >> 2) << 6;   // 0,64
    const int wj = (warp & 3) << 6;    // 0,64,128,192
    const int g  = lane >> 2;          // 0..7
    const int ti = lane & 3;           // 0..3

    float acc[4][8][4];
#pragma unroll
    for (int i = 0; i < 4; ++i)
#pragma unroll
        for (int j = 0; j < 8; ++j)
#pragma unroll
            for (int c = 0; c < 4; ++c) acc[i][j][c] = 0.0f;

    float4 rc0[2], rc1[2], ra0[2], ra1[2];

    auto loadA = [&](int c) {
        const int n0 = c << 5;
#pragma unroll
        for (int i = 0; i < 2; ++i) {
            const int u  = tid + (i << 8);   // 0..511
            const int np = u >> 5;           // 0..15
            const int q  = u & 31;           // float4 col
            const size_t ro = (size_t)(n0 + (np << 1)) * NNODES + m0;
            rc0[i] = *((const float4*)(Ac + ro) + q);
            rc1[i] = *((const float4*)(Ac + ro + NNODES) + q);
            ra0[i] = *((const float4*)(Aa + ro) + q);
            ra1[i] = *((const float4*)(Aa + ro + NNODES) + q);
        }
    };
    auto storeA = [&](int nb) {
#pragma unroll
        for (int i = 0; i < 2; ++i) {
            const int u  = tid + (i << 8);
            const int np = u >> 5;
            const int q  = u & 31;
            uint4 ua;
            ua.x = pack_h2(rc0[i].x * ra0[i].x, rc1[i].x * ra1[i].x);
            ua.y = pack_h2(rc0[i].y * ra0[i].y, rc1[i].y * ra1[i].y);
            ua.z = pack_h2(rc0[i].z * ra0[i].z, rc1[i].z * ra1[i].z);
            ua.w = pack_h2(rc0[i].w * ra0[i].w, rc1[i].w * ra1[i].w);
            *(uint4*)&As[nb][np][q << 2] = ua;
        }
    };
    auto loadB = [&](int c, int nb) {
        const uint32_t base = smem_u32(&Bs[nb][0][0]);
        const uint32_t* src = g_xh + (size_t)(b * 1024 + (c << 4)) * JDIM + j0;
#pragma unroll
        for (int i = 0; i < 4; ++i) {
            const int l  = tid + (i << 8);   // 0..1023
            const int np = l >> 6;           // 0..15
            const int o4 = (l & 63) << 2;    // uint32 offset in row
            cp16(base + (uint32_t)(np * 264 + o4) * 4, src + np * JDIM + o4);
        }
        asm volatile("cp.async.commit_group;" ::: "memory");
    };

    auto compute = [&](int buf) {
#pragma unroll
        for (int s = 0; s < 2; ++s) {          // 2 k-steps of 16
            const int r0 = (s << 3) + ti;
            const int r1 = r0 + 4;
            uint32_t af[4][4], bf[8][2];
#pragma unroll
            for (int i = 0; i < 4; ++i) {
                const int mi = wm + (i << 4);
                af[i][0] = As[buf][r0][mi + g];
                af[i][1] = As[buf][r0][mi + g + 8];
                af[i][2] = As[buf][r1][mi + g];
                af[i][3] = As[buf][r1][mi + g + 8];
            }
#pragma unroll
            for (int j = 0; j < 8; ++j) {
                const int nj = wj + (j << 3);
                bf[j][0] = Bs[buf][r0][nj + g];
                bf[j][1] = Bs[buf][r1][nj + g];
            }
#pragma unroll
            for (int i = 0; i < 4; ++i)
#pragma unroll
                for (int j = 0; j < 8; ++j)
                    mma_fp16(acc[i][j], af[i], bf[j]);
        }
    };

    // prologue
    loadA(0);
    loadB(0, 0);
    storeA(0);
    asm volatile("cp.async.wait_group 0;" ::: "memory");
    __syncthreads();

    for (int c = 0; c < 64; ++c) {
        const int buf = c & 1, nb = buf ^ 1;
        if (c < 63) {
            loadB(c + 1, nb);   // cp.async in flight during compute
            loadA(c + 1);       // LDGs in flight during compute
        }
        compute(buf);
        if (c < 63) {
            storeA(nb);
            asm volatile("cp.async.wait_group 0;" ::: "memory");
        }
        __syncthreads();
    }

    // Epilogue: acc c0:(g,2ti) c1:(g,2ti+1) c2:(g+8,2ti) c3:(g+8,2ti+1)
#pragma unroll
    for (int i = 0; i < 4; ++i) {
#pragma unroll
        for (int h = 0; h < 2; ++h) {
            const int row = m0 + wm + (i << 4) + g + (h << 3);
            float* orow = g_rhs
                        + (((size_t)b * NNODES + row) * KCHEB + k) * JDIM
                        + j0 + wj + (ti << 1);
#pragma unroll
            for (int j = 0; j < 8; ++j) {
                float2 v = make_float2(acc[i][j][h << 1], acc[i][j][(h << 1) + 1]);
                *(float2*)(orow + (j << 3)) = v;
            }
        }
    }
}

// ---------------------------------------------------------------------------
// Stage 2: out[b,m,o,t] = relu( sum_{k,f} rhs[b,m,k,f,t] * Theta[k,f,o] )
// ---------------------------------------------------------------------------
__global__ void __launch_bounds__(128)
stage2_kernel(const float* __restrict__ Theta, float* __restrict__ out)
{
    __shared__ float sW[KCHEB * 32 * FOUT];   // [kf][o]
    __shared__ float sR[2 * KCHEB * JDIM];    // 2 x [kf][t]

    const int tid = threadIdx.x;

#pragma unroll
    for (int i = 0; i < 12; ++i) {
        const int l = (tid + (i << 7)) << 2;
        *(float4*)&sW[l] = *(const float4*)(Theta + l);
    }
    const size_t bm0 = (size_t)blockIdx.x << 1;
    const float* rbase = g_rhs + bm0 * (KCHEB * JDIM);
#pragma unroll
    for (int i = 0; i < 9; ++i) {
        const int l = (tid + (i << 7)) << 2;
        *(float4*)&sR[l] = *(const float4*)(rbase + l);
    }
    __syncthreads();

    const int sub = tid >> 6;
    const int t64 = tid & 63;
    const int o0  = (t64 & 15) << 2;
    const int tb  = (t64 >> 4) * 6;
    const float* R = &sR[sub * (KCHEB * JDIM)];

    float acc[4][6];
#pragma unroll
    for (int i = 0; i < 4; ++i)
#pragma unroll
        for (int j = 0; j < 6; ++j) acc[i][j] = 0.0f;

#pragma unroll 4
    for (int kf = 0; kf < 96; ++kf) {
        const float4 wv = *(const float4*)&sW[(kf << 6) + o0];
        const float* rr = &R[kf * TDIM + tb];
#pragma unroll
        for (int j = 0; j < 6; ++j) {
            const float rv = rr[j];
            acc[0][j] = fmaf(wv.x, rv, acc[0][j]);
            acc[1][j] = fmaf(wv.y, rv, acc[1][j]);
            acc[2][j] = fmaf(wv.z, rv, acc[2][j]);
            acc[3][j] = fmaf(wv.w, rv, acc[3][j]);
        }
    }

    float* obase = out + (bm0 + sub) * (FOUT * TDIM);
#pragma unroll
    for (int i = 0; i < 4; ++i) {
        float* orow = obase + (o0 + i) * TDIM + tb;
#pragma unroll
        for (int j = 0; j < 6; j += 2)
            *(float2*)(orow + j) = make_float2(fmaxf(acc[i][j],     0.0f),
                                               fmaxf(acc[i][j + 1], 0.0f));
    }
}

// ---------------------------------------------------------------------------
extern "C" void kernel_launch(void* const* d_in, const int* in_sizes, int n_in,
                              void* d_out, int out_size)
{
    (void)in_sizes; (void)n_in; (void)out_size;
    const float* x     = (const float*)d_in[0];   // (16,2048,32,24)
    const float* att   = (const float*)d_in[1];   // (16,2048,2048)
    const float* cheb  = (const float*)d_in[2];   // (3,2048,2048)
    const float* Theta = (const float*)d_in[3];   // (3,32,64)
    float* out = (float*)d_out;                   // (16,2048,64,24)

    prepack_kernel<<<BATCH * 1024 * 192 / 256, 256>>>(x);
    dim3 g1(JDIM / 256, NNODES / 128, KCHEB * BATCH);   // (3, 16, 48)
    stage1_kernel<<<g1, 256>>>(att, cheb);
    stage2_kernel<<<(BATCH * NNODES) / 2, 128>>>(Theta, out);
}